// round 14
// baseline (speedup 1.0000x reference)
#include <cuda_runtime.h>
#include <cuda_bf16.h>
#include <cstdint>

// Problem constants
#define BB 64
#define SS 512
#define EE 256
#define HH 128
#define MM (BB * SS)          // 32768 rows
#define PAD 64                // padded neighbor-list width
#define PGRID 128             // persistent GEMM grid (layer-1 GEMM)

typedef unsigned long long ull;
typedef unsigned short u16;

// ---------------- device scratch --------------------------------------------
__device__ float g_Y[MM * HH];       // layer-1 GEMM output (fp32)
__device__ u16   g_ahi[MM * EE];     // activations hi bf16: buf0 / buf1 halves
__device__ u16   g_alo[MM * EE];     // activations lo bf16
__device__ u16   g_whi[128 * 256 + 2 * 128 * 128];   // W1|W2|W3 hi bf16
__device__ u16   g_wlo[128 * 256 + 2 * 128 * 128];   // W1|W2|W3 lo bf16
__device__ u16   g_nbr[MM * PAD];    // neighbor lists, indices pre-scaled by 32
__device__ int   g_cnt[MM];          // neighbor count padded to multiple of 8
__device__ float g_dinv[MM];         // 1 / (deg + 1)

#define W2_OFF (128 * 256)
#define W3_OFF (128 * 256 + 128 * 128)

// ---------------- packed f32x2 helpers --------------------------------------
__device__ __forceinline__ ull pack2(float x, float y) {
    ull r; asm("mov.b64 %0, {%1, %2};" : "=l"(r) : "f"(x), "f"(y)); return r;
}
__device__ __forceinline__ void unpack2(ull v, float& x, float& y) {
    asm("mov.b64 {%0, %1}, %2;" : "=f"(x), "=f"(y) : "l"(v));
}
__device__ __forceinline__ void fadd2(ull& d, ull a) {
    asm("add.rn.f32x2 %0, %0, %1;" : "+l"(d) : "l"(a));
}

// ---------------- mma.sync / cp.async plumbing -------------------------------
__device__ __forceinline__ uint32_t smem_to_u32(const void* p) {
    uint32_t a;
    asm("{ .reg .u64 t; cvta.to.shared.u64 t, %1; cvt.u32.u64 %0, t; }" : "=r"(a) : "l"(p));
    return a;
}
__device__ __forceinline__ void ldsm4(uint32_t& r0, uint32_t& r1, uint32_t& r2, uint32_t& r3,
                                      uint32_t addr) {
    asm volatile("ldmatrix.sync.aligned.m8n8.x4.shared.b16 {%0,%1,%2,%3}, [%4];"
                 : "=r"(r0), "=r"(r1), "=r"(r2), "=r"(r3) : "r"(addr));
}
__device__ __forceinline__ void ldsm2(uint32_t& r0, uint32_t& r1, uint32_t addr) {
    asm volatile("ldmatrix.sync.aligned.m8n8.x2.shared.b16 {%0,%1}, [%2];"
                 : "=r"(r0), "=r"(r1) : "r"(addr));
}
__device__ __forceinline__ void mma16816(float* c, const uint32_t* a, const uint32_t* b) {
    asm volatile("mma.sync.aligned.m16n8k16.row.col.f32.bf16.bf16.f32 "
                 "{%0,%1,%2,%3}, {%4,%5,%6,%7}, {%8,%9}, {%0,%1,%2,%3};"
                 : "+f"(c[0]), "+f"(c[1]), "+f"(c[2]), "+f"(c[3])
                 : "r"(a[0]), "r"(a[1]), "r"(a[2]), "r"(a[3]), "r"(b[0]), "r"(b[1]));
}
__device__ __forceinline__ void cp_async16(uint32_t dst, const void* src) {
    asm volatile("cp.async.cg.shared.global [%0], [%1], 16;" :: "r"(dst), "l"(src));
}
#define CP_COMMIT() asm volatile("cp.async.commit_group;" ::: "memory")
#define CP_WAIT0()  asm volatile("cp.async.wait_group 0;" ::: "memory")
#define CP_WAIT1()  asm volatile("cp.async.wait_group 1;" ::: "memory")

// bf16 hi/lo split packing
__device__ __forceinline__ uint2 bfpack(float4 v) {
    __nv_bfloat162 p0 = __floats2bfloat162_rn(v.x, v.y);
    __nv_bfloat162 p1 = __floats2bfloat162_rn(v.z, v.w);
    uint2 r; r.x = *(unsigned*)&p0; r.y = *(unsigned*)&p1; return r;
}
__device__ __forceinline__ float4 bfres(float4 v) {
    float4 r;
    r.x = v.x - __bfloat162float(__float2bfloat16_rn(v.x));
    r.y = v.y - __bfloat162float(__float2bfloat16_rn(v.y));
    r.z = v.z - __bfloat162float(__float2bfloat16_rn(v.z));
    r.w = v.w - __bfloat162float(__float2bfloat16_rn(v.w));
    return r;
}

// ---------------- 1) fused prep: embed+split | mask | weight-split | out init --
#define PREP_GRID (4096 + 4096 + 256 + 1)

__global__ void __launch_bounds__(256) prep_kernel(const int* __restrict__ sent,
                                                   const float4* __restrict__ emb4,
                                                   const float* __restrict__ adj,
                                                   const float* __restrict__ W1,
                                                   const float* __restrict__ W2,
                                                   const float* __restrict__ W3,
                                                   const float* __restrict__ bp,
                                                   float* __restrict__ out) {
    int blk = blockIdx.x;
    int t   = threadIdx.x;

    if (blk < 4096) {
#pragma unroll
        for (int h = 0; h < 2; h++) {
            int i = blk * 512 + h * 256 + t;
            int row = i >> 6;
            int c   = i & 63;
            int tok = sent[row];
            float4 v = emb4[(size_t)tok * 64 + c];
            ((uint2*)g_ahi)[(size_t)row * 64 + c] = bfpack(v);
            ((uint2*)g_alo)[(size_t)row * 64 + c] = bfpack(bfres(v));
        }
    } else if (blk < 8192) {
        int row  = (blk - 4096) * 8 + (t >> 5);
        int lane = t & 31;
        const float* a = adj + (size_t)row * SS;
        unsigned myw = 0;
#pragma unroll
        for (int j = 0; j < 16; j++) {
            unsigned m = __ballot_sync(0xFFFFFFFFu, a[j * 32 + lane] != 0.0f);
            if (lane == j) myw = m;
        }
        int c = (lane < 16) ? __popc(myw) : 0;
        int pre = c;
#pragma unroll
        for (int off = 1; off < 32; off <<= 1) {
            int n = __shfl_up_sync(0xFFFFFFFFu, pre, off);
            if (lane >= off) pre += n;
        }
        int excl  = pre - c;
        int total = __shfl_sync(0xFFFFFFFFu, pre, 15);

        u16* lst = g_nbr + (size_t)row * PAD;
        if (lane < 16) {
            unsigned m = myw;
            int o = excl;
            while (m) {
                int b = __ffs(m) - 1;
                m &= m - 1;
                if (o < PAD) lst[o] = (u16)((32 * lane + b) << 5);
                o++;
            }
        }
        if (lane == 0) {
            int tt = (total > PAD) ? PAD : total;
            int t8 = (tt + 7) & ~7;
            if (t8 > PAD) t8 = PAD;
            for (int i = tt; i < t8; i++) lst[i] = (u16)(512 << 5);
            g_cnt[row]  = t8;
            g_dinv[row] = 1.0f / (float)(total + 1);
        }
    } else if (blk < 8448) {
        int j = (blk - 8192) * 256 + t;       // 0..65535
        const float* src; int off;
        if (j < 32768)      { src = W1; off = j; }
        else if (j < 49152) { src = W2; off = j - 32768; }
        else                { src = W3; off = j - 49152; }
        float v = src[off];
        __nv_bfloat16 h = __float2bfloat16_rn(v);
        __nv_bfloat16 l = __float2bfloat16_rn(v - __bfloat162float(h));
        g_whi[j] = *(u16*)&h;
        g_wlo[j] = *(u16*)&l;
    } else {
        if (t < BB * 2) out[t] = bp[t & 1];
    }
}

// ---------------- 2) persistent HMMA GEMM (layer 1, K=256): Y = A @ W^T -------
#define LDAe   136
#define BT     (128 * LDAe * 2)

template <int Kt, int MT>
struct GS {
    static constexpr int NCHUNK = Kt / 128;
    static constexpr int NTILE  = MM / MT;
    static constexpr int A_HALF = MT * LDAe * 2;
    static constexpr int A_BUF  = 2 * A_HALF;
    static constexpr int A_BASE = NCHUNK * 2 * BT;
    static constexpr int TOTAL  = A_BASE + 2 * A_BUF;
    static constexpr int NW_N   = (MT == 128) ? 4 : 8;
    static constexpr int NW_M   = 16 / NW_N;
    static constexpr int COLS   = 128 / NW_N;
    static constexpr int NT     = COLS / 8;
    static constexpr int MAXT   = (NTILE + PGRID - 1) / PGRID;
};

template <int Kt, int MT>
__device__ __forceinline__ void issue_a(uint32_t sb_abuf, int tile, int chunk, int tid) {
    constexpr int A_HALF = MT * LDAe * 2;
    for (int i = tid; i < MT * 16; i += 512) {
        int r = i >> 4, ch = i & 15;
        uint32_t doff = (uint32_t)r * 272u + ch * 16;
        size_t src = ((size_t)tile * MT + r) * Kt + chunk * 128 + ch * 8;
        uint32_t dhi = sb_abuf + doff;
        uint32_t dlo = sb_abuf + (uint32_t)A_HALF + doff;
        cp_async16(dhi, g_ahi + src);
        cp_async16(dlo, g_alo + src);
    }
}

template <int Kt, int MT>
__global__ void __launch_bounds__(512, 1) pgemm_kernel(const u16* __restrict__ whi,
                                                       const u16* __restrict__ wlo) {
    using G = GS<Kt, MT>;
    extern __shared__ char smem[];
    uint32_t sb = smem_to_u32(smem);

    int tid = threadIdx.x;
    int wid = tid >> 5;
    int lane = tid & 31;
    int mi = wid % G::NW_M;
    int ni = wid / G::NW_M;

    int myT[G::MAXT]; int ntl = 0;
    for (int t = blockIdx.x; t < G::NTILE; t += PGRID) myT[ntl++] = t;
    int total_units = ntl * G::NCHUNK;

    for (int i = tid; i < G::NCHUNK * 2048; i += 512) {
        int c = i >> 11, r = (i >> 4) & 127, ch = i & 15;
        uint32_t doff = (uint32_t)r * 272u + ch * 16;
        size_t src = (size_t)r * Kt + c * 128 + ch * 8;
        cp_async16(sb + (uint32_t)(c * 2 + 0) * BT + doff, whi + src);
        cp_async16(sb + (uint32_t)(c * 2 + 1) * BT + doff, wlo + src);
    }
    CP_COMMIT();
    issue_a<Kt, MT>(sb + G::A_BASE, myT[0], 0, tid);
    CP_COMMIT();

    int arow_l = (lane & 15);
    int acol_l = (lane >> 4) << 3;
    int brow_l = (lane & 7) + ((lane >> 4) << 3);
    int bcol_l = ((lane >> 3) & 1) << 3;

    float acc[2][G::NT][4];

    for (int u = 0; u < total_units; u++) {
        int buf = u & 1;
        bool more = (u + 1 < total_units);
        if (more) {
            int nu = u + 1;
            issue_a<Kt, MT>(sb + G::A_BASE + (uint32_t)(nu & 1) * G::A_BUF,
                            myT[nu / G::NCHUNK], nu % G::NCHUNK, tid);
            CP_COMMIT();
            CP_WAIT1();
        } else {
            CP_WAIT0();
        }
        __syncthreads();

        int chunk = u % G::NCHUNK;
        if (chunk == 0) {
#pragma unroll
            for (int mt = 0; mt < 2; mt++)
#pragma unroll
                for (int nt = 0; nt < G::NT; nt++)
#pragma unroll
                    for (int q = 0; q < 4; q++) acc[mt][nt][q] = 0.0f;
        }

        uint32_t sb_ahi = sb + G::A_BASE + (uint32_t)buf * G::A_BUF;
        uint32_t sb_alo = sb_ahi + (uint32_t)G::A_HALF;
        uint32_t sb_bhi = sb + (uint32_t)(chunk * 2 + 0) * BT;
        uint32_t sb_blo = sb + (uint32_t)(chunk * 2 + 1) * BT;

#pragma unroll
        for (int ks = 0; ks < 8; ks++) {
            int k = ks * 16;
            uint32_t ahi[2][4], alo[2][4];
#pragma unroll
            for (int mt = 0; mt < 2; mt++) {
                uint32_t eoff = (uint32_t)((mi * 32 + mt * 16 + arow_l) * LDAe + k + acol_l) * 2;
                ldsm4(ahi[mt][0], ahi[mt][1], ahi[mt][2], ahi[mt][3], sb_ahi + eoff);
                ldsm4(alo[mt][0], alo[mt][1], alo[mt][2], alo[mt][3], sb_alo + eoff);
            }
            uint32_t bhi[G::NT][2], blo[G::NT][2];
#pragma unroll
            for (int t = 0; t < G::NT / 2; t++) {
                uint32_t eoff = (uint32_t)((ni * G::COLS + t * 16 + brow_l) * LDAe + k + bcol_l) * 2;
                ldsm4(bhi[2*t][0], bhi[2*t][1], bhi[2*t+1][0], bhi[2*t+1][1], sb_bhi + eoff);
                ldsm4(blo[2*t][0], blo[2*t][1], blo[2*t+1][0], blo[2*t+1][1], sb_blo + eoff);
            }
#pragma unroll
            for (int mt = 0; mt < 2; mt++)
#pragma unroll
                for (int nt = 0; nt < G::NT; nt++) {
                    mma16816(acc[mt][nt], ahi[mt], bhi[nt]);
                    mma16816(acc[mt][nt], alo[mt], bhi[nt]);
                    mma16816(acc[mt][nt], ahi[mt], blo[nt]);
                }
        }

        if (chunk == G::NCHUNK - 1) {
            size_t aBase = (size_t)myT[u / G::NCHUNK] * MT;
#pragma unroll
            for (int mt = 0; mt < 2; mt++) {
                size_t row0 = aBase + mi * 32 + mt * 16 + (lane >> 2);
#pragma unroll
                for (int nt = 0; nt < G::NT; nt++) {
                    int col = ni * G::COLS + nt * 8 + ((lane & 3) << 1);
                    *(float2*)&g_Y[row0 * 128 + col]       = make_float2(acc[mt][nt][0], acc[mt][nt][1]);
                    *(float2*)&g_Y[(row0 + 8) * 128 + col] = make_float2(acc[mt][nt][2], acc[mt][nt][3]);
                }
            }
        }
        __syncthreads();
    }
}

// ---------------- paired-neighbor agg core (shared by both agg paths) ---------
// lanes 0-15: even neighbors, features fl*4..fl*4+3; lanes 16-31: odd neighbors.
// Returns 4 accumulated features in (a01, a23) on lanes 0-15 (after shfl merge).
__device__ __forceinline__ void agg_row(const char* hsbase, const u16* L, int n8,
                                        int s, int half, int fl, int sh,
                                        ull& a01, ull& a23) {
    const char* hb = hsbase + fl * 16;
    float4 sv = make_float4(0.f, 0.f, 0.f, 0.f);
    if (half == 0) sv = *(const float4*)(hb + (size_t)s * 256);   // self term
    a01 = pack2(sv.x, sv.y);
    a23 = pack2(sv.z, sv.w);
    ull b01 = 0, b23 = 0;
    for (int k = 0; k < n8; k += 8) {
        int4 pk = *(const int4*)(L + k);
        int i0 = (pk.x >> sh) & 0xFFFF;
        int i1 = (pk.y >> sh) & 0xFFFF;
        int i2 = (pk.z >> sh) & 0xFFFF;
        int i3 = (pk.w >> sh) & 0xFFFF;
        float4 v0 = *(const float4*)(hb + i0 * 8);
        float4 v1 = *(const float4*)(hb + i1 * 8);
        float4 v2 = *(const float4*)(hb + i2 * 8);
        float4 v3 = *(const float4*)(hb + i3 * 8);
        fadd2(a01, pack2(v0.x, v0.y)); fadd2(a23, pack2(v0.z, v0.w));
        fadd2(b01, pack2(v1.x, v1.y)); fadd2(b23, pack2(v1.z, v1.w));
        fadd2(a01, pack2(v2.x, v2.y)); fadd2(a23, pack2(v2.z, v2.w));
        fadd2(b01, pack2(v3.x, v3.y)); fadd2(b23, pack2(v3.z, v3.w));
    }
    fadd2(a01, b01); fadd2(a23, b23);
    ull o01 = __shfl_down_sync(0xFFFFFFFFu, a01, 16);
    ull o23 = __shfl_down_sync(0xFFFFFFFFu, a23, 16);
    fadd2(a01, o01); fadd2(a23, o23);
}

// ---------------- 3) layer-1 aggregation (reads g_Y) --------------------------
#define SM_HS_F2   (513 * 32)
#define SM_CNT_OFF (SM_HS_F2 * 8)
#define SM_LST_OFF (SM_CNT_OFF + 512 * 4)
#define AGG_SMEM   (SM_LST_OFF + 512 * PAD * 2)

__global__ void __launch_bounds__(1024) agg_kernel(const float* __restrict__ bias) {
    extern __shared__ char smem[];
    float2* hs   = (float2*)smem;
    int*    scnt = (int*)(smem + SM_CNT_OFF);
    u16*    sl   = (u16*)(smem + SM_LST_OFF);

    int b  = blockIdx.x;
    int ch = blockIdx.y;
    int tid = threadIdx.x;

    const float2* Y2 = (const float2*)g_Y;

    for (int i = tid; i < SS * 32; i += 1024) {
        int t = i >> 5, f = i & 31;
        hs[i] = Y2[((size_t)(b * SS + t)) * 64 + ch * 32 + f];
    }
    if (tid < 32) hs[SS * 32 + tid] = make_float2(0.0f, 0.0f);
    if (tid < SS) scnt[tid] = g_cnt[b * SS + tid];
    {
        const int4* src = (const int4*)(g_nbr + (size_t)b * SS * PAD);
        int4* dst = (int4*)sl;
        for (int i = tid; i < SS * PAD / 8; i += 1024) dst[i] = src[i];
    }
    __syncthreads();

    int lane = tid & 31, warp = tid >> 5;
    int half = lane >> 4, fl = lane & 15, sh = half << 4;
    float4 bv4 = ((const float4*)bias)[ch * 16 + fl];

    for (int s = warp; s < SS; s += 32) {
        int row = b * SS + s;
        ull a01, a23;
        agg_row((const char*)smem, sl + s * PAD, scnt[s], s, half, fl, sh, a01, a23);
        if (half == 0) {
            float sx, sy, sz, sw;
            unpack2(a01, sx, sy); unpack2(a23, sz, sw);
            float di = g_dinv[row];
            float ox = fmaxf((sx + 2.0f * bv4.x) * di, 0.0f);
            float oy = fmaxf((sy + 2.0f * bv4.y) * di, 0.0f);
            float oz = fmaxf((sz + 2.0f * bv4.z) * di, 0.0f);
            float ow = fmaxf((sw + 2.0f * bv4.w) * di, 0.0f);
            float4 v = make_float4(ox, oy, oz, ow);
            uint2 hp = bfpack(v);
            uint2 lp = bfpack(bfres(v));
            size_t o = (size_t)row * 32 + ch * 16 + fl;   // uint2 units
            ((uint2*)g_ahi)[o] = hp;
            ((uint2*)g_alo)[o] = lp;
        }
    }
}

// ---------------- 4) fused GEMM + AGG (layers 2,3) ----------------------------
// CTA = (b, ch). 1024 threads, ALL warps compute mma (4M x 8N, warp tile m16n8).
// A chunks (64 rows) double-buffered 2-deep via cp.async; lists streamed into
// freed A buffers during the last 2 chunks. Y tile written straight to smem hs.
#define FS_WHI 131328
#define FS_WLO 147712
#define FS_A   164096
#define FS_CNT 229632
#define FUSED_SMEM 231680

template <bool LAST>
__global__ void __launch_bounds__(1024, 1) fused_kernel(
    const u16* __restrict__ ahi, const u16* __restrict__ alo,
    unsigned* __restrict__ ohi, unsigned* __restrict__ olo,
    const u16* __restrict__ whi, const u16* __restrict__ wlo,
    const float* __restrict__ bias, const float* __restrict__ Wp,
    float* __restrict__ out)
{
    extern __shared__ char smem[];
    uint32_t sb = smem_to_u32(smem);
    int b = blockIdx.x, ch = blockIdx.y;
    int tid = threadIdx.x, wid = tid >> 5, lane = tid & 31;
    int rowBase = b * SS;
    float2* hs = (float2*)smem;
    int* scnt = (int*)(smem + FS_CNT);
    u16* sl = (u16*)(smem + FS_A);

    // per-thread staging coords (one 16B chunk per thread per tile)
    int r_ld = tid >> 4, c_ld = tid & 15;
    uint32_t doff = (uint32_t)(r_ld * 256) + (uint32_t)((c_ld ^ (r_ld & 15)) << 4);

    // ---- prologue: group0 = W + counts + A chunk0; group1 = A chunk1
    {
        size_t wsrc = (size_t)(ch * 64 + r_ld) * 128 + c_ld * 8;
        cp_async16(sb + FS_WHI + doff, whi + wsrc);
        cp_async16(sb + FS_WLO + doff, wlo + wsrc);
        if (tid < 128) cp_async16(sb + FS_CNT + tid * 16, (const char*)(g_cnt + rowBase) + tid * 16);
        size_t asrc = ((size_t)(rowBase + r_ld)) * 128 + c_ld * 8;
        cp_async16(sb + FS_A + doff, ahi + asrc);
        cp_async16(sb + FS_A + 16384 + doff, alo + asrc);
        CP_COMMIT();
        size_t asrc1 = ((size_t)(rowBase + 64 + r_ld)) * 128 + c_ld * 8;
        cp_async16(sb + FS_A + 32768 + doff, ahi + asrc1);
        cp_async16(sb + FS_A + 32768 + 16384 + doff, alo + asrc1);
        CP_COMMIT();
    }
    if (tid < 64) ((float*)smem)[512 * 64 + tid] = 0.0f;    // hs dummy row 512

    int mi = wid & 3, ni = wid >> 2;
    int ar = mi * 16 + (lane & 15);
    int arx = ar & 15;
    int ac = lane >> 4;
    int br = ni * 8 + (lane & 7);
    int brx = br & 15;
    int bc = (lane >> 3) & 1;
    uint32_t arow_off = (uint32_t)ar * 256;
    uint32_t brow_off = (uint32_t)br * 256;

    for (int g = 0; g < 8; g++) {
        CP_WAIT1();
        __syncthreads();
        // ---- compute chunk g from buf g&1
        uint32_t sbh = sb + FS_A + (uint32_t)(g & 1) * 32768;
        uint32_t sbl = sbh + 16384;
        float acc[4] = {0, 0, 0, 0};
#pragma unroll
        for (int ks = 0; ks < 8; ks++) {
            uint32_t aoff = arow_off + (uint32_t)(((2 * ks + ac) ^ arx) << 4);
            uint32_t boff = brow_off + (uint32_t)(((2 * ks + bc) ^ brx) << 4);
            uint32_t a_hi[4], a_lo[4], b_hi[2], b_lo[2];
            ldsm4(a_hi[0], a_hi[1], a_hi[2], a_hi[3], sbh + aoff);
            ldsm4(a_lo[0], a_lo[1], a_lo[2], a_lo[3], sbl + aoff);
            ldsm2(b_hi[0], b_hi[1], sb + FS_WHI + boff);
            ldsm2(b_lo[0], b_lo[1], sb + FS_WLO + boff);
            mma16816(acc, a_hi, b_hi);
            mma16816(acc, a_lo, b_hi);
            mma16816(acc, a_hi, b_lo);
        }
        // write Y into hs
        int t0 = g * 64 + mi * 16 + (lane >> 2);
        int f0 = ni * 4 + (lane & 3);
        hs[t0 * 32 + f0]       = make_float2(acc[0], acc[1]);
        hs[(t0 + 8) * 32 + f0] = make_float2(acc[2], acc[3]);
        __syncthreads();
        // ---- issue next work into buf g&1
        if (g < 6) {
            size_t asrc = ((size_t)(rowBase + (g + 2) * 64 + r_ld)) * 128 + c_ld * 8;
            uint32_t dbase = sb + FS_A + (uint32_t)(g & 1) * 32768;
            cp_async16(dbase + doff, ahi + asrc);
            cp_async16(dbase + 16384 + doff, alo + asrc);
            CP_COMMIT();
        } else {
            // lists half (g-6) into the freed buffer
            int h = g - 6;
            const char* lsrc = (const char*)(g_nbr + (size_t)rowBase * PAD) + h * 32768;
            for (int i = tid; i < 2048; i += 1024)
                cp_async16(sb + FS_A + h * 32768 + i * 16, lsrc + i * 16);
            CP_COMMIT();
        }
    }
    CP_WAIT0();
    __syncthreads();

    // ---- AGG phase (paired-neighbor LDS.128)
    int half = lane >> 4, fl = lane & 15, sh = half << 4;
    float4 bv4 = ((const float4*)bias)[ch * 16 + fl];
    float m0 = 0.f, m1 = 0.f, m2 = 0.f, m3 = 0.f;

    for (int s = wid; s < SS; s += 32) {
        int row = rowBase + s;
        ull a01, a23;
        agg_row((const char*)smem, sl + s * PAD, scnt[s], s, half, fl, sh, a01, a23);
        if (half == 0) {
            float sx, sy, sz, sw;
            unpack2(a01, sx, sy); unpack2(a23, sz, sw);
            float di = g_dinv[row];
            float ox = fmaxf((sx + 2.0f * bv4.x) * di, 0.0f);
            float oy = fmaxf((sy + 2.0f * bv4.y) * di, 0.0f);
            float oz = fmaxf((sz + 2.0f * bv4.z) * di, 0.0f);
            float ow = fmaxf((sw + 2.0f * bv4.w) * di, 0.0f);
            if (LAST) {
                m0 = fmaxf(m0, ox); m1 = fmaxf(m1, oy);
                m2 = fmaxf(m2, oz); m3 = fmaxf(m3, ow);
            } else {
                float4 v = make_float4(ox, oy, oz, ow);
                uint2 hp = bfpack(v);
                uint2 lp = bfpack(bfres(v));
                size_t o = (size_t)row * 32 + ch * 16 + fl;   // uint2 units
                ((uint2*)ohi)[o] = hp;
                ((uint2*)olo)[o] = lp;
            }
        }
    }

    if (LAST) {
        __syncthreads();
        float* red = (float*)(smem + FS_A);     // lists done; reuse
        if (half == 0) {
            red[wid * 64 + fl * 4 + 0] = m0;
            red[wid * 64 + fl * 4 + 1] = m1;
            red[wid * 64 + fl * 4 + 2] = m2;
            red[wid * 64 + fl * 4 + 3] = m3;
        }
        __syncthreads();
        if (wid == 0) {
            float p0m = 0.0f, p1m = 0.0f;
#pragma unroll
            for (int w = 0; w < 32; w++) {
                p0m = fmaxf(p0m, red[w * 64 + lane * 2]);
                p1m = fmaxf(p1m, red[w * 64 + lane * 2 + 1]);
            }
            int j0 = ch * 64 + lane * 2;
            float p0 = p0m * Wp[0 * 128 + j0] + p1m * Wp[0 * 128 + j0 + 1];
            float p1 = p0m * Wp[1 * 128 + j0] + p1m * Wp[1 * 128 + j0 + 1];
#pragma unroll
            for (int off = 16; off > 0; off >>= 1) {
                p0 += __shfl_down_sync(0xFFFFFFFFu, p0, off);
                p1 += __shfl_down_sync(0xFFFFFFFFu, p1, off);
            }
            if (lane == 0) {
                atomicAdd(&out[b * 2 + 0], p0);
                atomicAdd(&out[b * 2 + 1], p1);
            }
        }
    }
}

// ---------------- launcher ---------------------------------------------------
extern "C" void kernel_launch(void* const* d_in, const int* in_sizes, int n_in,
                              void* d_out, int out_size) {
    const int*   sent = (const int*)  d_in[0];
    const float* adj  = (const float*)d_in[1];
    const float* emb  = (const float*)d_in[2];
    const float* W1   = (const float*)d_in[3];
    const float* b1   = (const float*)d_in[4];
    const float* W2   = (const float*)d_in[5];
    const float* b2   = (const float*)d_in[6];
    const float* W3   = (const float*)d_in[7];
    const float* b3   = (const float*)d_in[8];
    const float* Wp   = (const float*)d_in[9];
    const float* bp   = (const float*)d_in[10];
    float* out = (float*)d_out;

    cudaFuncSetAttribute(agg_kernel, cudaFuncAttributeMaxDynamicSharedMemorySize, AGG_SMEM);
    cudaFuncSetAttribute((const void*)pgemm_kernel<EE, 64>,
                         cudaFuncAttributeMaxDynamicSharedMemorySize, GS<EE, 64>::TOTAL);
    cudaFuncSetAttribute((const void*)fused_kernel<false>,
                         cudaFuncAttributeMaxDynamicSharedMemorySize, FUSED_SMEM);
    cudaFuncSetAttribute((const void*)fused_kernel<true>,
                         cudaFuncAttributeMaxDynamicSharedMemorySize, FUSED_SMEM);

    u16 *whi_d, *wlo_d, *ahi_d, *alo_d;
    cudaGetSymbolAddress((void**)&whi_d, g_whi);
    cudaGetSymbolAddress((void**)&wlo_d, g_wlo);
    cudaGetSymbolAddress((void**)&ahi_d, g_ahi);
    cudaGetSymbolAddress((void**)&alo_d, g_alo);
    u16* ahi1 = ahi_d + (size_t)MM * 128;
    u16* alo1 = alo_d + (size_t)MM * 128;

    prep_kernel<<<PREP_GRID, 256>>>(sent, (const float4*)emb, adj, W1, W2, W3, bp, out);

    // layer 1: persistent GEMM (K=256) + agg -> buf0
    pgemm_kernel<EE, 64><<<PGRID, 512, GS<EE, 64>::TOTAL>>>(whi_d, wlo_d);
    agg_kernel<<<dim3(BB, 2), 1024, AGG_SMEM>>>(b1);

    // layer 2: fused GEMM+agg, buf0 -> buf1
    fused_kernel<false><<<dim3(BB, 2), 1024, FUSED_SMEM>>>(
        ahi_d, alo_d, (unsigned*)ahi1, (unsigned*)alo1,
        whi_d + W2_OFF, wlo_d + W2_OFF, b2, nullptr, nullptr);

    // layer 3: fused GEMM+agg+pool+logits, buf1 -> out
    fused_kernel<true><<<dim3(BB, 2), 1024, FUSED_SMEM>>>(
        ahi1, alo1, nullptr, nullptr,
        whi_d + W3_OFF, wlo_d + W3_OFF, b3, Wp, out);
}

// round 15
// speedup vs baseline: 1.1426x; 1.1426x over previous
#include <cuda_runtime.h>
#include <cuda_bf16.h>
#include <cstdint>

// Problem constants
#define BB 64
#define SS 512
#define EE 256
#define HH 128
#define MM (BB * SS)          // 32768 rows
#define PAD 64                // padded neighbor-list width
#define PGRID 128             // persistent GEMM grid (layer-1 GEMM)

typedef unsigned long long ull;
typedef unsigned short u16;

// ---------------- device scratch --------------------------------------------
__device__ float g_Y[MM * HH];       // layer-1 GEMM output (fp32)
__device__ u16   g_ahi[MM * EE];     // activations hi bf16: buf0 / buf1 halves
__device__ u16   g_alo[MM * EE];     // activations lo bf16
__device__ u16   g_whi[128 * 256 + 2 * 128 * 128];   // W1|W2|W3 hi bf16
__device__ u16   g_wlo[128 * 256 + 2 * 128 * 128];   // W1|W2|W3 lo bf16
__device__ u16   g_nbr[MM * PAD];    // neighbor lists, indices pre-scaled by 32; fully padded
__device__ int   g_cnt[MM];          // neighbor count padded to multiple of 8
__device__ float g_dinv[MM];         // 1 / (deg + 1)

#define W2_OFF (128 * 256)
#define W3_OFF (128 * 256 + 128 * 128)

// ---------------- packed f32x2 helpers --------------------------------------
__device__ __forceinline__ void unpack2(ull v, float& x, float& y) {
    asm("mov.b64 {%0, %1}, %2;" : "=f"(x), "=f"(y) : "l"(v));
}
__device__ __forceinline__ void fadd2(ull& d, ull a) {
    asm("add.rn.f32x2 %0, %0, %1;" : "+l"(d) : "l"(a));
}

// ---------------- mma.sync / cp.async plumbing -------------------------------
__device__ __forceinline__ uint32_t smem_to_u32(const void* p) {
    uint32_t a;
    asm("{ .reg .u64 t; cvta.to.shared.u64 t, %1; cvt.u32.u64 %0, t; }" : "=r"(a) : "l"(p));
    return a;
}
__device__ __forceinline__ void ldsm4(uint32_t& r0, uint32_t& r1, uint32_t& r2, uint32_t& r3,
                                      uint32_t addr) {
    asm volatile("ldmatrix.sync.aligned.m8n8.x4.shared.b16 {%0,%1,%2,%3}, [%4];"
                 : "=r"(r0), "=r"(r1), "=r"(r2), "=r"(r3) : "r"(addr));
}
__device__ __forceinline__ void mma16816(float* c, const uint32_t* a, const uint32_t* b) {
    asm volatile("mma.sync.aligned.m16n8k16.row.col.f32.bf16.bf16.f32 "
                 "{%0,%1,%2,%3}, {%4,%5,%6,%7}, {%8,%9}, {%0,%1,%2,%3};"
                 : "+f"(c[0]), "+f"(c[1]), "+f"(c[2]), "+f"(c[3])
                 : "r"(a[0]), "r"(a[1]), "r"(a[2]), "r"(a[3]), "r"(b[0]), "r"(b[1]));
}
__device__ __forceinline__ void cp_async16(uint32_t dst, const void* src) {
    asm volatile("cp.async.cg.shared.global [%0], [%1], 16;" :: "r"(dst), "l"(src));
}
#define CP_COMMIT() asm volatile("cp.async.commit_group;" ::: "memory")
#define CP_WAIT0()  asm volatile("cp.async.wait_group 0;" ::: "memory")
#define CP_WAIT1()  asm volatile("cp.async.wait_group 1;" ::: "memory")

// bf16 hi/lo split packing
__device__ __forceinline__ uint2 bfpack(float4 v) {
    __nv_bfloat162 p0 = __floats2bfloat162_rn(v.x, v.y);
    __nv_bfloat162 p1 = __floats2bfloat162_rn(v.z, v.w);
    uint2 r; r.x = *(unsigned*)&p0; r.y = *(unsigned*)&p1; return r;
}
__device__ __forceinline__ float4 bfres(float4 v) {
    float4 r;
    r.x = v.x - __bfloat162float(__float2bfloat16_rn(v.x));
    r.y = v.y - __bfloat162float(__float2bfloat16_rn(v.y));
    r.z = v.z - __bfloat162float(__float2bfloat16_rn(v.z));
    r.w = v.w - __bfloat162float(__float2bfloat16_rn(v.w));
    return r;
}

// ---------------- row-paired agg core ----------------------------------------
// hs8 = smem base + fl*16 (this lane's 16B feature chunk). Accumulates a row's
// neighbor sum into (a01, a23) as 2 packed f32x2. Indices pre-scaled by 32:
// byte offset = idx * 8 = row * 256. Padded entries point at zeroed row 512.
__device__ __forceinline__ void agg_core(const char* hs8, const u16* L, int n8,
                                         ull& a01, ull& a23) {
    ull b01 = 0, b23 = 0;
    for (int k = 0; k < n8; k += 8) {
        int4 pk = *(const int4*)(L + k);
        int j0 = pk.x & 0xFFFF, j1 = ((unsigned)pk.x) >> 16;
        int j2 = pk.y & 0xFFFF, j3 = ((unsigned)pk.y) >> 16;
        int j4 = pk.z & 0xFFFF, j5 = ((unsigned)pk.z) >> 16;
        int j6 = pk.w & 0xFFFF, j7 = ((unsigned)pk.w) >> 16;
        ulonglong2 v0 = *(const ulonglong2*)(hs8 + j0 * 8);
        ulonglong2 v1 = *(const ulonglong2*)(hs8 + j1 * 8);
        ulonglong2 v2 = *(const ulonglong2*)(hs8 + j2 * 8);
        ulonglong2 v3 = *(const ulonglong2*)(hs8 + j3 * 8);
        fadd2(a01, v0.x); fadd2(a23, v0.y);
        fadd2(b01, v1.x); fadd2(b23, v1.y);
        fadd2(a01, v2.x); fadd2(a23, v2.y);
        fadd2(b01, v3.x); fadd2(b23, v3.y);
        ulonglong2 v4 = *(const ulonglong2*)(hs8 + j4 * 8);
        ulonglong2 v5 = *(const ulonglong2*)(hs8 + j5 * 8);
        ulonglong2 v6 = *(const ulonglong2*)(hs8 + j6 * 8);
        ulonglong2 v7 = *(const ulonglong2*)(hs8 + j7 * 8);
        fadd2(a01, v4.x); fadd2(a23, v4.y);
        fadd2(b01, v5.x); fadd2(b23, v5.y);
        fadd2(a01, v6.x); fadd2(a23, v6.y);
        fadd2(b01, v7.x); fadd2(b23, v7.y);
    }
    fadd2(a01, b01); fadd2(a23, b23);
}

// ---------------- 1) fused prep: embed+split | mask | weight-split | out init --
#define PREP_GRID (4096 + 4096 + 256 + 1)

__global__ void __launch_bounds__(256) prep_kernel(const int* __restrict__ sent,
                                                   const float4* __restrict__ emb4,
                                                   const float* __restrict__ adj,
                                                   const float* __restrict__ W1,
                                                   const float* __restrict__ W2,
                                                   const float* __restrict__ W3,
                                                   const float* __restrict__ bp,
                                                   float* __restrict__ out) {
    int blk = blockIdx.x;
    int t   = threadIdx.x;

    if (blk < 4096) {
#pragma unroll
        for (int h = 0; h < 2; h++) {
            int i = blk * 512 + h * 256 + t;
            int row = i >> 6;
            int c   = i & 63;
            int tok = sent[row];
            float4 v = emb4[(size_t)tok * 64 + c];
            ((uint2*)g_ahi)[(size_t)row * 64 + c] = bfpack(v);
            ((uint2*)g_alo)[(size_t)row * 64 + c] = bfpack(bfres(v));
        }
    } else if (blk < 8192) {
        int row  = (blk - 4096) * 8 + (t >> 5);
        int lane = t & 31;
        const float* a = adj + (size_t)row * SS;
        unsigned myw = 0;
#pragma unroll
        for (int j = 0; j < 16; j++) {
            unsigned m = __ballot_sync(0xFFFFFFFFu, a[j * 32 + lane] != 0.0f);
            if (lane == j) myw = m;
        }
        int c = (lane < 16) ? __popc(myw) : 0;
        int pre = c;
#pragma unroll
        for (int off = 1; off < 32; off <<= 1) {
            int n = __shfl_up_sync(0xFFFFFFFFu, pre, off);
            if (lane >= off) pre += n;
        }
        int excl  = pre - c;
        int total = __shfl_sync(0xFFFFFFFFu, pre, 15);

        u16* lst = g_nbr + (size_t)row * PAD;
        if (lane < 16) {
            unsigned m = myw;
            int o = excl;
            while (m) {
                int b = __ffs(m) - 1;
                m &= m - 1;
                if (o < PAD) lst[o] = (u16)((32 * lane + b) << 5);
                o++;
            }
        }
        int tt = (total > PAD) ? PAD : total;
        for (int i = tt + lane; i < PAD; i += 32) lst[i] = (u16)(512 << 5);  // full pad
        if (lane == 0) {
            int t8 = (tt + 7) & ~7;
            if (t8 > PAD) t8 = PAD;
            g_cnt[row]  = t8;
            g_dinv[row] = 1.0f / (float)(total + 1);
        }
    } else if (blk < 8448) {
        int j = (blk - 8192) * 256 + t;       // 0..65535
        const float* src; int off;
        if (j < 32768)      { src = W1; off = j; }
        else if (j < 49152) { src = W2; off = j - 32768; }
        else                { src = W3; off = j - 49152; }
        float v = src[off];
        __nv_bfloat16 h = __float2bfloat16_rn(v);
        __nv_bfloat16 l = __float2bfloat16_rn(v - __bfloat162float(h));
        g_whi[j] = *(u16*)&h;
        g_wlo[j] = *(u16*)&l;
    } else {
        if (t < BB * 2) out[t] = bp[t & 1];
    }
}

// ---------------- 2) persistent HMMA GEMM (layer 1, K=256): Y = A @ W^T -------
#define LDAe   136
#define BT     (128 * LDAe * 2)

template <int Kt, int MT>
struct GS {
    static constexpr int NCHUNK = Kt / 128;
    static constexpr int NTILE  = MM / MT;
    static constexpr int A_HALF = MT * LDAe * 2;
    static constexpr int A_BUF  = 2 * A_HALF;
    static constexpr int A_BASE = NCHUNK * 2 * BT;
    static constexpr int TOTAL  = A_BASE + 2 * A_BUF;
    static constexpr int NW_N   = (MT == 128) ? 4 : 8;
    static constexpr int NW_M   = 16 / NW_N;
    static constexpr int COLS   = 128 / NW_N;
    static constexpr int NT     = COLS / 8;
    static constexpr int MAXT   = (NTILE + PGRID - 1) / PGRID;
};

template <int Kt, int MT>
__device__ __forceinline__ void issue_a(uint32_t sb_abuf, int tile, int chunk, int tid) {
    constexpr int A_HALF = MT * LDAe * 2;
    for (int i = tid; i < MT * 16; i += 512) {
        int r = i >> 4, ch = i & 15;
        uint32_t doff = (uint32_t)r * 272u + ch * 16;
        size_t src = ((size_t)tile * MT + r) * Kt + chunk * 128 + ch * 8;
        uint32_t dhi = sb_abuf + doff;
        uint32_t dlo = sb_abuf + (uint32_t)A_HALF + doff;
        cp_async16(dhi, g_ahi + src);
        cp_async16(dlo, g_alo + src);
    }
}

template <int Kt, int MT>
__global__ void __launch_bounds__(512, 1) pgemm_kernel(const u16* __restrict__ whi,
                                                       const u16* __restrict__ wlo) {
    using G = GS<Kt, MT>;
    extern __shared__ char smem[];
    uint32_t sb = smem_to_u32(smem);

    int tid = threadIdx.x;
    int wid = tid >> 5;
    int lane = tid & 31;
    int mi = wid % G::NW_M;
    int ni = wid / G::NW_M;

    int myT[G::MAXT]; int ntl = 0;
    for (int t = blockIdx.x; t < G::NTILE; t += PGRID) myT[ntl++] = t;
    int total_units = ntl * G::NCHUNK;

    for (int i = tid; i < G::NCHUNK * 2048; i += 512) {
        int c = i >> 11, r = (i >> 4) & 127, ch = i & 15;
        uint32_t doff = (uint32_t)r * 272u + ch * 16;
        size_t src = (size_t)r * Kt + c * 128 + ch * 8;
        cp_async16(sb + (uint32_t)(c * 2 + 0) * BT + doff, whi + src);
        cp_async16(sb + (uint32_t)(c * 2 + 1) * BT + doff, wlo + src);
    }
    CP_COMMIT();
    issue_a<Kt, MT>(sb + G::A_BASE, myT[0], 0, tid);
    CP_COMMIT();

    int arow_l = (lane & 15);
    int acol_l = (lane >> 4) << 3;
    int brow_l = (lane & 7) + ((lane >> 4) << 3);
    int bcol_l = ((lane >> 3) & 1) << 3;

    float acc[2][G::NT][4];

    for (int u = 0; u < total_units; u++) {
        int buf = u & 1;
        bool more = (u + 1 < total_units);
        if (more) {
            int nu = u + 1;
            issue_a<Kt, MT>(sb + G::A_BASE + (uint32_t)(nu & 1) * G::A_BUF,
                            myT[nu / G::NCHUNK], nu % G::NCHUNK, tid);
            CP_COMMIT();
            CP_WAIT1();
        } else {
            CP_WAIT0();
        }
        __syncthreads();

        int chunk = u % G::NCHUNK;
        if (chunk == 0) {
#pragma unroll
            for (int mt = 0; mt < 2; mt++)
#pragma unroll
                for (int nt = 0; nt < G::NT; nt++)
#pragma unroll
                    for (int q = 0; q < 4; q++) acc[mt][nt][q] = 0.0f;
        }

        uint32_t sb_ahi = sb + G::A_BASE + (uint32_t)buf * G::A_BUF;
        uint32_t sb_alo = sb_ahi + (uint32_t)G::A_HALF;
        uint32_t sb_bhi = sb + (uint32_t)(chunk * 2 + 0) * BT;
        uint32_t sb_blo = sb + (uint32_t)(chunk * 2 + 1) * BT;

#pragma unroll
        for (int ks = 0; ks < 8; ks++) {
            int k = ks * 16;
            uint32_t ahi[2][4], alo[2][4];
#pragma unroll
            for (int mt = 0; mt < 2; mt++) {
                uint32_t eoff = (uint32_t)((mi * 32 + mt * 16 + arow_l) * LDAe + k + acol_l) * 2;
                ldsm4(ahi[mt][0], ahi[mt][1], ahi[mt][2], ahi[mt][3], sb_ahi + eoff);
                ldsm4(alo[mt][0], alo[mt][1], alo[mt][2], alo[mt][3], sb_alo + eoff);
            }
            uint32_t bhi[G::NT][2], blo[G::NT][2];
#pragma unroll
            for (int t = 0; t < G::NT / 2; t++) {
                uint32_t eoff = (uint32_t)((ni * G::COLS + t * 16 + brow_l) * LDAe + k + bcol_l) * 2;
                ldsm4(bhi[2*t][0], bhi[2*t][1], bhi[2*t+1][0], bhi[2*t+1][1], sb_bhi + eoff);
                ldsm4(blo[2*t][0], blo[2*t][1], blo[2*t+1][0], blo[2*t+1][1], sb_blo + eoff);
            }
#pragma unroll
            for (int mt = 0; mt < 2; mt++)
#pragma unroll
                for (int nt = 0; nt < G::NT; nt++) {
                    mma16816(acc[mt][nt], ahi[mt], bhi[nt]);
                    mma16816(acc[mt][nt], alo[mt], bhi[nt]);
                    mma16816(acc[mt][nt], ahi[mt], blo[nt]);
                }
        }

        if (chunk == G::NCHUNK - 1) {
            size_t aBase = (size_t)myT[u / G::NCHUNK] * MT;
#pragma unroll
            for (int mt = 0; mt < 2; mt++) {
                size_t row0 = aBase + mi * 32 + mt * 16 + (lane >> 2);
#pragma unroll
                for (int nt = 0; nt < G::NT; nt++) {
                    int col = ni * G::COLS + nt * 8 + ((lane & 3) << 1);
                    *(float2*)&g_Y[row0 * 128 + col]       = make_float2(acc[mt][nt][0], acc[mt][nt][1]);
                    *(float2*)&g_Y[(row0 + 8) * 128 + col] = make_float2(acc[mt][nt][2], acc[mt][nt][3]);
                }
            }
        }
        __syncthreads();
    }
}

// ---------------- 3) layer-1 aggregation (reads g_Y), row-paired core ---------
#define SM_HS_F2   (513 * 32)
#define SM_CNT_OFF (SM_HS_F2 * 8)
#define SM_LST_OFF (SM_CNT_OFF + 512 * 4)
#define AGG_SMEM   (SM_LST_OFF + 512 * PAD * 2)

__global__ void __launch_bounds__(1024) agg_kernel(const float* __restrict__ bias) {
    extern __shared__ char smem[];
    float2* hs   = (float2*)smem;
    int*    scnt = (int*)(smem + SM_CNT_OFF);
    u16*    sl   = (u16*)(smem + SM_LST_OFF);

    int b  = blockIdx.x;
    int ch = blockIdx.y;
    int tid = threadIdx.x;

    const float2* Y2 = (const float2*)g_Y;

    for (int i = tid; i < SS * 32; i += 1024) {
        int t = i >> 5, f = i & 31;
        hs[i] = Y2[((size_t)(b * SS + t)) * 64 + ch * 32 + f];
    }
    if (tid < 32) hs[SS * 32 + tid] = make_float2(0.0f, 0.0f);
    if (tid < SS) scnt[tid] = g_cnt[b * SS + tid];
    {
        const int4* src = (const int4*)(g_nbr + (size_t)b * SS * PAD);
        int4* dst = (int4*)sl;
        for (int i = tid; i < SS * PAD / 8; i += 1024) dst[i] = src[i];
    }
    __syncthreads();

    int lane = tid & 31, warp = tid >> 5;
    int half = lane >> 4, fl = lane & 15;
    const char* hs8 = (const char*)smem + fl * 16;
    float4 bv4 = ((const float4*)bias)[ch * 16 + fl];

    for (int i = warp; i < 256; i += 32) {
        int s = i + (half << 8);
        int row = b * SS + s;
        int n8 = max(scnt[i], scnt[i + 256]);
        ulonglong2 sv = *(const ulonglong2*)(hs8 + (size_t)s * 256);   // self term
        ull a01 = sv.x, a23 = sv.y;
        agg_core(hs8, sl + s * PAD, n8, a01, a23);

        float sx, sy, sz, sw;
        unpack2(a01, sx, sy); unpack2(a23, sz, sw);
        float di = g_dinv[row];
        float ox = fmaxf((sx + 2.0f * bv4.x) * di, 0.0f);
        float oy = fmaxf((sy + 2.0f * bv4.y) * di, 0.0f);
        float oz = fmaxf((sz + 2.0f * bv4.z) * di, 0.0f);
        float ow = fmaxf((sw + 2.0f * bv4.w) * di, 0.0f);
        float4 v = make_float4(ox, oy, oz, ow);
        uint2 hp = bfpack(v);
        uint2 lp = bfpack(bfres(v));
        size_t o = (size_t)row * 32 + ch * 16 + fl;   // uint2 units
        ((uint2*)g_ahi)[o] = hp;
        ((uint2*)g_alo)[o] = lp;
    }
}

// ---------------- 4) fused GEMM + AGG (layers 2,3) ----------------------------
// R13 GEMM phase (warp-specialized loaders) + row-paired agg core.
#define FS_WHI 131328
#define FS_WLO 147712
#define FS_A   164096
#define FS_CNT 229632
#define FUSED_SMEM 231680

template <bool LAST>
__global__ void __launch_bounds__(1024, 1) fused_kernel(
    const u16* __restrict__ ahi, const u16* __restrict__ alo,
    unsigned* __restrict__ ohi, unsigned* __restrict__ olo,
    const u16* __restrict__ whi, const u16* __restrict__ wlo,
    const float* __restrict__ bias, const float* __restrict__ Wp,
    float* __restrict__ out)
{
    extern __shared__ char smem[];
    uint32_t sb = smem_to_u32(smem);
    int b = blockIdx.x, ch = blockIdx.y;
    int tid = threadIdx.x, wid = tid >> 5, lane = tid & 31;
    int rowBase = b * SS;
    float2* hs = (float2*)smem;
    int* scnt = (int*)(smem + FS_CNT);
    u16* sl = (u16*)(smem + FS_A);

    bool loader = (wid >= 16);
    int lt = tid & 511;

    if (loader) {
        for (int i = lt; i < 1024; i += 512) {
            int r = i >> 4, c = i & 15;
            uint32_t doff = (uint32_t)(r * 256) + (uint32_t)((c ^ (r & 15)) << 4);
            size_t src = (size_t)(ch * 64 + r) * 128 + c * 8;
            cp_async16(sb + FS_WHI + doff, whi + src);
            cp_async16(sb + FS_WLO + doff, wlo + src);
        }
        if (lt < 128) cp_async16(sb + FS_CNT + lt * 16, (const char*)(g_cnt + rowBase) + lt * 16);
        for (int i = lt; i < 1024; i += 512) {
            int r = i >> 4, c = i & 15;
            uint32_t doff = (uint32_t)(r * 256) + (uint32_t)((c ^ (r & 15)) << 4);
            size_t src = ((size_t)(rowBase + r)) * 128 + c * 8;
            cp_async16(sb + FS_A + doff, ahi + src);
            cp_async16(sb + FS_A + 16384 + doff, alo + src);
        }
        CP_COMMIT(); CP_WAIT0();
        if (lt < 64) ((float*)smem)[512 * 64 + lt] = 0.0f;    // hs dummy row 512
    }
    __syncthreads();

    for (int g = 0; g < 8; g++) {
        if (loader) {
            if (g < 7) {
                int gg = g + 1;
                uint32_t dbase = sb + FS_A + (uint32_t)(gg & 1) * 32768;
                for (int i = lt; i < 1024; i += 512) {
                    int r = i >> 4, c = i & 15;
                    uint32_t doff = (uint32_t)(r * 256) + (uint32_t)((c ^ (r & 15)) << 4);
                    size_t src = ((size_t)(rowBase + gg * 64 + r)) * 128 + c * 8;
                    cp_async16(dbase + doff, ahi + src);
                    cp_async16(dbase + 16384 + doff, alo + src);
                }
            } else {
                const char* lsrc = (const char*)(g_nbr + (size_t)rowBase * PAD);
                for (int i = lt; i < 2048; i += 512)
                    cp_async16(sb + FS_A + i * 16, lsrc + i * 16);
            }
            CP_COMMIT(); CP_WAIT0();
        } else {
            int mi = wid & 3, ni = wid >> 2;
            uint32_t sbh = sb + FS_A + (uint32_t)(g & 1) * 32768;
            uint32_t sbl = sbh + 16384;
            float acc0[4] = {0, 0, 0, 0}, acc1[4] = {0, 0, 0, 0};
            int ar = mi * 16 + (lane & 15);
            int arx = ar & 15;
            int br = ni * 16 + (lane & 7) + ((lane >> 4) << 3);
            int brx = br & 15;
            uint32_t arow_off = (uint32_t)ar * 256;
            uint32_t brow_off = (uint32_t)br * 256;
            int ac_base = lane >> 4;
            int bc_base = (lane >> 3) & 1;
#pragma unroll
            for (int ks = 0; ks < 8; ks++) {
                uint32_t aoff = arow_off + (uint32_t)(((2 * ks + ac_base) ^ arx) << 4);
                uint32_t boff = brow_off + (uint32_t)(((2 * ks + bc_base) ^ brx) << 4);
                uint32_t a_hi[4], a_lo[4], b_hi[4], b_lo[4];
                ldsm4(a_hi[0], a_hi[1], a_hi[2], a_hi[3], sbh + aoff);
                ldsm4(a_lo[0], a_lo[1], a_lo[2], a_lo[3], sbl + aoff);
                ldsm4(b_hi[0], b_hi[1], b_hi[2], b_hi[3], sb + FS_WHI + boff);
                ldsm4(b_lo[0], b_lo[1], b_lo[2], b_lo[3], sb + FS_WLO + boff);
                mma16816(acc0, a_hi, b_hi);
                mma16816(acc0, a_lo, b_hi);
                mma16816(acc0, a_hi, b_lo);
                mma16816(acc1, a_hi, b_hi + 2);
                mma16816(acc1, a_lo, b_hi + 2);
                mma16816(acc1, a_hi, b_lo + 2);
            }
            int t0 = g * 64 + mi * 16 + (lane >> 2);
            int f0 = ni * 8 + (lane & 3);
            hs[t0 * 32 + f0]           = make_float2(acc0[0], acc0[1]);
            hs[(t0 + 8) * 32 + f0]     = make_float2(acc0[2], acc0[3]);
            hs[t0 * 32 + f0 + 4]       = make_float2(acc1[0], acc1[1]);
            hs[(t0 + 8) * 32 + f0 + 4] = make_float2(acc1[2], acc1[3]);
        }
        __syncthreads();
    }
    if (loader) {
        const char* lsrc = (const char*)(g_nbr + (size_t)rowBase * PAD) + 32768;
        for (int i = lt; i < 2048; i += 512)
            cp_async16(sb + FS_A + 32768 + i * 16, lsrc + i * 16);
        CP_COMMIT(); CP_WAIT0();
    }
    __syncthreads();

    // ---- AGG phase (row-paired core, all 32 warps, all lanes active)
    int half = lane >> 4, fl = lane & 15;
    const char* hs8 = (const char*)smem + fl * 16;
    float4 bv4 = ((const float4*)bias)[ch * 16 + fl];
    float m0 = 0.f, m1 = 0.f, m2 = 0.f, m3 = 0.f;

    for (int i = wid; i < 256; i += 32) {
        int s = i + (half << 8);
        int row = rowBase + s;
        int n8 = max(scnt[i], scnt[i + 256]);
        ulonglong2 sv = *(const ulonglong2*)(hs8 + (size_t)s * 256);   // self term
        ull a01 = sv.x, a23 = sv.y;
        agg_core(hs8, sl + s * PAD, n8, a01, a23);

        float sx, sy, sz, sw;
        unpack2(a01, sx, sy); unpack2(a23, sz, sw);
        float di = g_dinv[row];
        float ox = fmaxf((sx + 2.0f * bv4.x) * di, 0.0f);
        float oy = fmaxf((sy + 2.0f * bv4.y) * di, 0.0f);
        float oz = fmaxf((sz + 2.0f * bv4.z) * di, 0.0f);
        float ow = fmaxf((sw + 2.0f * bv4.w) * di, 0.0f);
        if (LAST) {
            m0 = fmaxf(m0, ox); m1 = fmaxf(m1, oy);
            m2 = fmaxf(m2, oz); m3 = fmaxf(m3, ow);
        } else {
            float4 v = make_float4(ox, oy, oz, ow);
            uint2 hp = bfpack(v);
            uint2 lp = bfpack(bfres(v));
            size_t o = (size_t)row * 32 + ch * 16 + fl;   // uint2 units
            ((uint2*)ohi)[o] = hp;
            ((uint2*)olo)[o] = lp;
        }
    }

    if (LAST) {
        // merge halves (same features, different rows) via shfl, then cross-warp
        m0 = fmaxf(m0, __shfl_down_sync(0xFFFFFFFFu, m0, 16));
        m1 = fmaxf(m1, __shfl_down_sync(0xFFFFFFFFu, m1, 16));
        m2 = fmaxf(m2, __shfl_down_sync(0xFFFFFFFFu, m2, 16));
        m3 = fmaxf(m3, __shfl_down_sync(0xFFFFFFFFu, m3, 16));
        __syncthreads();
        float* red = (float*)(smem + FS_A);     // lists done; reuse
        if (half == 0) {
            red[wid * 64 + fl * 4 + 0] = m0;
            red[wid * 64 + fl * 4 + 1] = m1;
            red[wid * 64 + fl * 4 + 2] = m2;
            red[wid * 64 + fl * 4 + 3] = m3;
        }
        __syncthreads();
        if (wid == 0) {
            float p0m = 0.0f, p1m = 0.0f;
#pragma unroll
            for (int w = 0; w < 32; w++) {
                p0m = fmaxf(p0m, red[w * 64 + lane * 2]);
                p1m = fmaxf(p1m, red[w * 64 + lane * 2 + 1]);
            }
            int j0 = ch * 64 + lane * 2;
            float p0 = p0m * Wp[0 * 128 + j0] + p1m * Wp[0 * 128 + j0 + 1];
            float p1 = p0m * Wp[1 * 128 + j0] + p1m * Wp[1 * 128 + j0 + 1];
#pragma unroll
            for (int off = 16; off > 0; off >>= 1) {
                p0 += __shfl_down_sync(0xFFFFFFFFu, p0, off);
                p1 += __shfl_down_sync(0xFFFFFFFFu, p1, off);
            }
            if (lane == 0) {
                atomicAdd(&out[b * 2 + 0], p0);
                atomicAdd(&out[b * 2 + 1], p1);
            }
        }
    }
}

// ---------------- launcher ---------------------------------------------------
extern "C" void kernel_launch(void* const* d_in, const int* in_sizes, int n_in,
                              void* d_out, int out_size) {
    const int*   sent = (const int*)  d_in[0];
    const float* adj  = (const float*)d_in[1];
    const float* emb  = (const float*)d_in[2];
    const float* W1   = (const float*)d_in[3];
    const float* b1   = (const float*)d_in[4];
    const float* W2   = (const float*)d_in[5];
    const float* b2   = (const float*)d_in[6];
    const float* W3   = (const float*)d_in[7];
    const float* b3   = (const float*)d_in[8];
    const float* Wp   = (const float*)d_in[9];
    const float* bp   = (const float*)d_in[10];
    float* out = (float*)d_out;

    cudaFuncSetAttribute(agg_kernel, cudaFuncAttributeMaxDynamicSharedMemorySize, AGG_SMEM);
    cudaFuncSetAttribute((const void*)pgemm_kernel<EE, 64>,
                         cudaFuncAttributeMaxDynamicSharedMemorySize, GS<EE, 64>::TOTAL);
    cudaFuncSetAttribute((const void*)fused_kernel<false>,
                         cudaFuncAttributeMaxDynamicSharedMemorySize, FUSED_SMEM);
    cudaFuncSetAttribute((const void*)fused_kernel<true>,
                         cudaFuncAttributeMaxDynamicSharedMemorySize, FUSED_SMEM);

    u16 *whi_d, *wlo_d, *ahi_d, *alo_d;
    cudaGetSymbolAddress((void**)&whi_d, g_whi);
    cudaGetSymbolAddress((void**)&wlo_d, g_wlo);
    cudaGetSymbolAddress((void**)&ahi_d, g_ahi);
    cudaGetSymbolAddress((void**)&alo_d, g_alo);
    u16* ahi1 = ahi_d + (size_t)MM * 128;
    u16* alo1 = alo_d + (size_t)MM * 128;

    prep_kernel<<<PREP_GRID, 256>>>(sent, (const float4*)emb, adj, W1, W2, W3, bp, out);

    // layer 1: persistent GEMM (K=256) + agg -> buf0
    pgemm_kernel<EE, 64><<<PGRID, 512, GS<EE, 64>::TOTAL>>>(whi_d, wlo_d);
    agg_kernel<<<dim3(BB, 2), 1024, AGG_SMEM>>>(b1);

    // layer 2: fused GEMM+agg, buf0 -> buf1
    fused_kernel<false><<<dim3(BB, 2), 1024, FUSED_SMEM>>>(
        ahi_d, alo_d, (unsigned*)ahi1, (unsigned*)alo1,
        whi_d + W2_OFF, wlo_d + W2_OFF, b2, nullptr, nullptr);

    // layer 3: fused GEMM+agg+pool+logits, buf1 -> out
    fused_kernel<true><<<dim3(BB, 2), 1024, FUSED_SMEM>>>(
        ahi1, alo1, nullptr, nullptr,
        whi_d + W3_OFF, wlo_d + W3_OFF, b3, Wp, out);
}